// round 6
// baseline (speedup 1.0000x reference)
#include <cuda_runtime.h>
#include <cuda_bf16.h>
#include <cstdint>

#define N_NODES 50000
#define N_RELS  8
#define IN_DIM  128
#define OUT_DIM 128
#define N_EDGES 800000
#define M_TILES ((N_NODES + 127) / 128)   // 391

// Scratch (__device__ globals: allocation-free rule)
__device__ __align__(16) float g_h[(size_t)N_RELS * N_NODES * OUT_DIM]; // 204.8 MB
__device__ float g_counts[N_RELS * N_NODES];                            // 1.6 MB
__device__ __align__(16) __nv_bfloat16 g_wt_hi[N_RELS * 128 * 128];     // W^T hi [r][o][k]
__device__ __align__(16) __nv_bfloat16 g_wt_lo[N_RELS * 128 * 128];     // W^T lo [r][o][k]

// ---------------------------------------------------------------------------
// helpers (baseline PTX ISA — safe for plain sm_103 ptx target)
// ---------------------------------------------------------------------------
__device__ __forceinline__ uint32_t smem_u32(const void* p) {
    uint32_t a;
    asm("{ .reg .u64 t; cvta.to.shared.u64 t, %1; cvt.u32.u64 %0, t; }"
        : "=r"(a) : "l"(p));
    return a;
}

__device__ __forceinline__ void ldsm4(uint32_t* r, uint32_t addr) {
    asm volatile("ldmatrix.sync.aligned.m8n8.x4.shared.b16 {%0,%1,%2,%3}, [%4];"
                 : "=r"(r[0]), "=r"(r[1]), "=r"(r[2]), "=r"(r[3]) : "r"(addr));
}

__device__ __forceinline__ void mma_bf16(float* d, const uint32_t* a, const uint32_t* b) {
    asm volatile(
        "mma.sync.aligned.m16n8k16.row.col.f32.bf16.bf16.f32 "
        "{%0,%1,%2,%3}, {%4,%5,%6,%7}, {%8,%9}, {%0,%1,%2,%3};"
        : "+f"(d[0]), "+f"(d[1]), "+f"(d[2]), "+f"(d[3])
        : "r"(a[0]), "r"(a[1]), "r"(a[2]), "r"(a[3]), "r"(b[0]), "r"(b[1]));
}

__device__ __forceinline__ void cp16(uint32_t dst, const void* src) {
    asm volatile("cp.async.ca.shared.global [%0], [%1], 16;"
                 :: "r"(dst), "l"(src) : "memory");
}
#define CP_COMMIT() asm volatile("cp.async.commit_group;" ::: "memory")
#define CP_WAIT(n)  asm volatile("cp.async.wait_group %0;" :: "n"(n) : "memory")

// tile row = 256B (128 bf16) = 16 chunks of 16B; chunk' = chunk ^ (row&7)
__device__ __forceinline__ uint32_t sw_off(int row, int chunk) {
    return (uint32_t)(row * 256 + ((chunk ^ (row & 7)) << 4));
}

// SMEM: Ahi 32KB | Alo 32KB | Bbuf0 (hi32+lo32) | Bbuf1 (hi32+lo32) = 192KB
#define SM_AH 0
#define SM_AL 32768
#define SM_B  65536           // + buf*65536 ; hi at +0, lo at +32768
#define SMEM_TOTAL 196608

// ---------------------------------------------------------------------------
// Kernel 1: out = bias, counts = 0
// ---------------------------------------------------------------------------
__global__ void init_kernel(float* __restrict__ out, const float* __restrict__ bias) {
    int idx = blockIdx.x * blockDim.x + threadIdx.x;
    int stride = gridDim.x * blockDim.x;
    const int total = N_NODES * OUT_DIM;
    for (int i = idx; i < total; i += stride)
        out[i] = bias[i & (OUT_DIM - 1)];
    for (int i = idx; i < N_RELS * N_NODES; i += stride)
        g_counts[i] = 0.0f;
}

// ---------------------------------------------------------------------------
// Kernel 2: counts[rel*N + tgt] += 1
// ---------------------------------------------------------------------------
__global__ void count_kernel(const int* __restrict__ triples) {
    int e = blockIdx.x * blockDim.x + threadIdx.x;
    if (e < N_EDGES) {
        int rel = triples[e * 3 + 1];
        int tgt = triples[e * 3 + 2];
        atomicAdd(&g_counts[rel * N_NODES + tgt], 1.0f);
    }
}

// ---------------------------------------------------------------------------
// Kernel 2b: W [r][k][o] fp32 -> Wt hi/lo [r][o][k] bf16 (transpose + split)
// ---------------------------------------------------------------------------
__global__ void split_w_kernel(const float* __restrict__ W) {
    int idx = blockIdx.x * blockDim.x + threadIdx.x;
    if (idx >= N_RELS * 128 * 128) return;
    int r = idx >> 14;
    int k = (idx >> 7) & 127;
    int o = idx & 127;
    float x = W[idx];
    __nv_bfloat16 hi = __float2bfloat16(x);
    __nv_bfloat16 lo = __float2bfloat16(x - __bfloat162float(hi));
    int dst = (r << 14) + (o << 7) + k;
    g_wt_hi[dst] = hi;
    g_wt_lo[dst] = lo;
}

// ---------------------------------------------------------------------------
// Kernel 3: split-bf16 GEMM: h[r] = features @ W[r] for all r.
//   CTA = 128-row m-tile. A converted ONCE; loop over 8 rels with
//   double-buffered B via cp.async. 8 warps x (32m x 64n) per rel.
// ---------------------------------------------------------------------------
__global__ void __launch_bounds__(256)
gemm_mma_kernel(const float* __restrict__ A) {
    extern __shared__ char smem[];
    const int m0 = blockIdx.x * 128;
    const int tid = threadIdx.x;
    const int wid = tid >> 5;
    const int lid = tid & 31;
    const uint32_t sb = smem_u32(smem);

    // ---- prefetch B for rel 0 into buf 0 (cp.async, overlaps A convert) ----
    {
        const __nv_bfloat16* Bh = g_wt_hi;
        const __nv_bfloat16* Bl = g_wt_lo;
#pragma unroll
        for (int i = 0; i < 8; i++) {
            int cid = tid + i * 256;      // 2048 chunks
            int row = cid >> 4;
            int chunk = cid & 15;
            uint32_t so = sw_off(row, chunk);
            cp16(sb + SM_B + so,         Bh + (row << 7) + (chunk << 3));
            cp16(sb + SM_B + 32768 + so, Bl + (row << 7) + (chunk << 3));
        }
        CP_COMMIT();
    }

    // ---- fill A hi/lo (128 rows x 128 bf16 each), converted once ----
#pragma unroll
    for (int i = 0; i < 8; i++) {
        int cid = tid + i * 256;          // 2048 chunks
        int row = cid >> 4;
        int chunk = cid & 15;
        uint32_t so = sw_off(row, chunk);
        int grow = m0 + row;
        if (grow >= N_NODES) grow = 0;    // junk rows; epilogue guards
        const float* p = A + ((size_t)grow << 7) + (chunk << 3);
        float4 x0 = *(const float4*)p;
        float4 x1 = *(const float4*)(p + 4);
        float f[8] = {x0.x, x0.y, x0.z, x0.w, x1.x, x1.y, x1.z, x1.w};
        uint32_t ph[4], pl[4];
#pragma unroll
        for (int j = 0; j < 4; j++) {
            __nv_bfloat162 th, tl;
            float a = f[2 * j], b = f[2 * j + 1];
            th.x = __float2bfloat16(a);
            th.y = __float2bfloat16(b);
            tl.x = __float2bfloat16(a - __bfloat162float(th.x));
            tl.y = __float2bfloat16(b - __bfloat162float(th.y));
            ph[j] = *reinterpret_cast<uint32_t*>(&th);
            pl[j] = *reinterpret_cast<uint32_t*>(&tl);
        }
        *(uint4*)(smem + SM_AH + so) = make_uint4(ph[0], ph[1], ph[2], ph[3]);
        *(uint4*)(smem + SM_AL + so) = make_uint4(pl[0], pl[1], pl[2], pl[3]);
    }

    // ---- per-lane ldmatrix addresses ----
    const int wm = wid & 3;          // 4 m-tiles of 32 rows
    const int wn = wid >> 2;         // 2 n-tiles of 64 cols
    const int a_row = wm * 32 + (lid & 15);
    const int a_kc  = lid >> 4;
    const int a_and = a_row & 7;
    const uint32_t a_base = sb + (uint32_t)(a_row * 256);
    const int b_row = wn * 64 + ((lid >> 4) << 3) + (lid & 7);
    const int b_kc  = (lid >> 3) & 1;
    const int b_and = b_row & 7;     // invariant under +16*g
    const uint32_t b_row_off = (uint32_t)(b_row * 256);

    const int col0 = wn * 64 + (lid & 3) * 2;
    const int row_lo = m0 + wm * 32 + (lid >> 2);

#pragma unroll 1
    for (int r = 0; r < N_RELS; r++) {
        const uint32_t bbuf = sb + SM_B + (uint32_t)(r & 1) * 65536;

        __syncthreads();   // prev iteration's MMA done before overwriting its buffer
        // ---- prefetch B for rel r+1 into the other buffer ----
        if (r + 1 < N_RELS) {
            const __nv_bfloat16* Bh = g_wt_hi + ((r + 1) << 14);
            const __nv_bfloat16* Bl = g_wt_lo + ((r + 1) << 14);
            const uint32_t nbuf = sb + SM_B + (uint32_t)((r + 1) & 1) * 65536;
#pragma unroll
            for (int i = 0; i < 8; i++) {
                int cid = tid + i * 256;
                int row = cid >> 4;
                int chunk = cid & 15;
                uint32_t so = sw_off(row, chunk);
                cp16(nbuf + so,         Bh + (row << 7) + (chunk << 3));
                cp16(nbuf + 32768 + so, Bl + (row << 7) + (chunk << 3));
            }
            CP_COMMIT();
            CP_WAIT(1);    // B_r complete (B_{r+1} may be in flight)
        } else {
            CP_WAIT(0);
        }
        __syncthreads();   // B_r visible to all (and A on first iter)

        float acc[2][8][4];
#pragma unroll
        for (int mt = 0; mt < 2; mt++)
#pragma unroll
            for (int nn = 0; nn < 8; nn++)
#pragma unroll
                for (int c = 0; c < 4; c++) acc[mt][nn][c] = 0.0f;

#pragma unroll
        for (int s = 0; s < 8; s++) {
            uint32_t Ah[2][4], Al[2][4], Bh4[4][4], Bl4[4][4];
            const uint32_t ac = (uint32_t)(((s * 2 + a_kc) ^ a_and) << 4);
            const uint32_t bc = (uint32_t)(((s * 2 + b_kc) ^ b_and) << 4);
#pragma unroll
            for (int t2 = 0; t2 < 2; t2++) {
                ldsm4(Ah[t2], a_base + SM_AH + t2 * 4096 + ac);
                ldsm4(Al[t2], a_base + SM_AL + t2 * 4096 + ac);
            }
#pragma unroll
            for (int g = 0; g < 4; g++) {
                ldsm4(Bh4[g], bbuf + b_row_off + g * 4096 + bc);
                ldsm4(Bl4[g], bbuf + 32768 + b_row_off + g * 4096 + bc);
            }
#pragma unroll
            for (int g = 0; g < 4; g++) {
#pragma unroll
                for (int half = 0; half < 2; half++) {
                    const int nn = g * 2 + half;
                    const uint32_t* bh = &Bh4[g][half * 2];
                    const uint32_t* bl = &Bl4[g][half * 2];
#pragma unroll
                    for (int mt = 0; mt < 2; mt++) {
                        mma_bf16(acc[mt][nn], Ah[mt], bh);
                        mma_bf16(acc[mt][nn], Ah[mt], bl);
                        mma_bf16(acc[mt][nn], Al[mt], bh);
                    }
                }
            }
        }

        // ---- epilogue: write fp32 h[r] tile (overlaps next rel's cp.async) ----
        float* H = g_h + ((size_t)r * N_NODES << 7);
#pragma unroll
        for (int mt = 0; mt < 2; mt++) {
            int row = row_lo + mt * 16;
            if (row < N_NODES) {
                float* Hp = H + ((size_t)row << 7) + col0;
#pragma unroll
                for (int nn = 0; nn < 8; nn++)
                    *(float2*)(Hp + nn * 8) = make_float2(acc[mt][nn][0], acc[mt][nn][1]);
            }
            if (row + 8 < N_NODES) {
                float* Hp = H + ((size_t)(row + 8) << 7) + col0;
#pragma unroll
                for (int nn = 0; nn < 8; nn++)
                    *(float2*)(Hp + nn * 8) = make_float2(acc[mt][nn][2], acc[mt][nn][3]);
            }
        }
    }
}

// ---------------------------------------------------------------------------
// Kernel 4: 4 lanes/edge; each lane owns a contiguous 128B segment.
//   out[tgt] += h[rel,src] / counts[rel*N+tgt]
// ---------------------------------------------------------------------------
__global__ void edge_kernel(const int* __restrict__ triples, float* __restrict__ out) {
    int t = blockIdx.x * blockDim.x + threadIdx.x;
    int e = t >> 2;
    int p = t & 3;
    if (e >= N_EDGES) return;

    int src = triples[e * 3 + 0];
    int rel = triples[e * 3 + 1];
    int tgt = triples[e * 3 + 2];

    float val = 1.0f / g_counts[rel * N_NODES + tgt];

    const float4* f = (const float4*)(g_h + (((size_t)rel * N_NODES + src) << 7)) + p * 8;
    float4 v[8];
#pragma unroll
    for (int i = 0; i < 8; i++) v[i] = f[i];
#pragma unroll
    for (int i = 0; i < 8; i++) {
        v[i].x *= val; v[i].y *= val; v[i].z *= val; v[i].w *= val;
    }

    float4* o = (float4*)(out + ((size_t)tgt << 7)) + p * 8;
#pragma unroll
    for (int i = 0; i < 8; i++)
        asm volatile("red.global.add.v4.f32 [%0], {%1, %2, %3, %4};"
                     :: "l"(o + i), "f"(v[i].x), "f"(v[i].y), "f"(v[i].z), "f"(v[i].w)
                     : "memory");
}

// ---------------------------------------------------------------------------
extern "C" void kernel_launch(void* const* d_in, const int* in_sizes, int n_in,
                              void* d_out, int out_size) {
    const int*   triples  = (const int*)d_in[0];    // [E, 3] (src, rel, tgt)
    const float* features = (const float*)d_in[1];  // [N, 128]
    const float* weights  = (const float*)d_in[2];  // [8, 128, 128]
    const float* bias     = (const float*)d_in[3];  // [128]
    float* out = (float*)d_out;                     // [N, 128]
    (void)in_sizes; (void)n_in; (void)out_size;

    cudaFuncSetAttribute(gemm_mma_kernel,
                         cudaFuncAttributeMaxDynamicSharedMemorySize, SMEM_TOTAL);

    init_kernel<<<1024, 256>>>(out, bias);
    count_kernel<<<(N_EDGES + 255) / 256, 256>>>(triples);
    split_w_kernel<<<(N_RELS * 128 * 128 + 255) / 256, 256>>>(weights);

    gemm_mma_kernel<<<M_TILES, 256, SMEM_TOTAL>>>(features);

    edge_kernel<<<(N_EDGES * 4 + 255) / 256, 256>>>(triples, out);
}

// round 8
// speedup vs baseline: 1.5119x; 1.5119x over previous
#include <cuda_runtime.h>
#include <cuda_bf16.h>
#include <cstdint>

#define N_NODES 50000
#define N_RELS  8
#define IN_DIM  128
#define OUT_DIM 128
#define N_EDGES 800000
#define M_TILES ((N_NODES + 127) / 128)   // 391
#define SRC_BLK 2048
#define N_BUCKETS ((N_NODES + SRC_BLK - 1) / SRC_BLK)   // 25

// Scratch (__device__ globals: allocation-free rule)
__device__ __align__(16) float g_h[(size_t)N_RELS * N_NODES * OUT_DIM]; // 204.8 MB
__device__ float g_counts[N_RELS * N_NODES];                            // 1.6 MB
__device__ __align__(16) __nv_bfloat16 g_wt_hi[N_RELS * 128 * 128];     // W^T hi [r][o][k]
__device__ __align__(16) __nv_bfloat16 g_wt_lo[N_RELS * 128 * 128];     // W^T lo [r][o][k]
__device__ int g_bkt_hist[N_BUCKETS];
__device__ int g_bkt_cursor[N_BUCKETS];
__device__ __align__(16) int4 g_es[N_EDGES];   // {src, tgt, val_bits, rel}, src-block order

// ---------------------------------------------------------------------------
// helpers (baseline PTX ISA — safe for plain sm_103 ptx target)
// ---------------------------------------------------------------------------
__device__ __forceinline__ uint32_t smem_u32(const void* p) {
    uint32_t a;
    asm("{ .reg .u64 t; cvta.to.shared.u64 t, %1; cvt.u32.u64 %0, t; }"
        : "=r"(a) : "l"(p));
    return a;
}

__device__ __forceinline__ void ldsm4(uint32_t* r, uint32_t addr) {
    asm volatile("ldmatrix.sync.aligned.m8n8.x4.shared.b16 {%0,%1,%2,%3}, [%4];"
                 : "=r"(r[0]), "=r"(r[1]), "=r"(r[2]), "=r"(r[3]) : "r"(addr));
}

__device__ __forceinline__ void mma_bf16(float* d, const uint32_t* a, const uint32_t* b) {
    asm volatile(
        "mma.sync.aligned.m16n8k16.row.col.f32.bf16.bf16.f32 "
        "{%0,%1,%2,%3}, {%4,%5,%6,%7}, {%8,%9}, {%0,%1,%2,%3};"
        : "+f"(d[0]), "+f"(d[1]), "+f"(d[2]), "+f"(d[3])
        : "r"(a[0]), "r"(a[1]), "r"(a[2]), "r"(a[3]), "r"(b[0]), "r"(b[1]));
}

// tile row = 256B (128 bf16) = 16 chunks of 16B; chunk' = chunk ^ (row&7)
__device__ __forceinline__ uint32_t sw_off(int row, int chunk) {
    return (uint32_t)(row * 256 + ((chunk ^ (row & 7)) << 4));
}

// SMEM: Ahi 32KB | Alo 32KB | Bhi 32KB | Blo 32KB = 128KB
#define SM_AH 0
#define SM_AL 32768
#define SM_BH 65536
#define SM_BL 98304
#define SMEM_TOTAL 131072

// ---------------------------------------------------------------------------
// Kernel 1: out = bias, counts = 0, bucket hist/cursor = 0
// ---------------------------------------------------------------------------
__global__ void init_kernel(float* __restrict__ out, const float* __restrict__ bias) {
    int idx = blockIdx.x * blockDim.x + threadIdx.x;
    int stride = gridDim.x * blockDim.x;
    const int total = N_NODES * OUT_DIM;
    for (int i = idx; i < total; i += stride)
        out[i] = bias[i & (OUT_DIM - 1)];
    for (int i = idx; i < N_RELS * N_NODES; i += stride)
        g_counts[i] = 0.0f;
    if (idx < N_BUCKETS) { g_bkt_hist[idx] = 0; g_bkt_cursor[idx] = 0; }
}

// ---------------------------------------------------------------------------
// Kernel 2: counts[rel*N + tgt] += 1, plus src-block histogram
// ---------------------------------------------------------------------------
__global__ void count_kernel(const int* __restrict__ triples) {
    __shared__ int sh[N_BUCKETS];
    if (threadIdx.x < N_BUCKETS) sh[threadIdx.x] = 0;
    __syncthreads();
    int e = blockIdx.x * blockDim.x + threadIdx.x;
    if (e < N_EDGES) {
        int src = triples[e * 3 + 0];
        int rel = triples[e * 3 + 1];
        int tgt = triples[e * 3 + 2];
        atomicAdd(&g_counts[rel * N_NODES + tgt], 1.0f);
        atomicAdd(&sh[src / SRC_BLK], 1);
    }
    __syncthreads();
    if (threadIdx.x < N_BUCKETS)
        atomicAdd(&g_bkt_hist[threadIdx.x], sh[threadIdx.x]);
}

// ---------------------------------------------------------------------------
// Kernel 2c: exclusive prefix of bucket histogram -> cursors
// ---------------------------------------------------------------------------
__global__ void offsets_kernel() {
    if (threadIdx.x == 0 && blockIdx.x == 0) {
        int s = 0;
        for (int b = 0; b < N_BUCKETS; b++) {
            g_bkt_cursor[b] = s;
            s += g_bkt_hist[b];
        }
    }
}

// ---------------------------------------------------------------------------
// Kernel 2d: bucket edges by src-block into compact {src,tgt,val,rel}
// ---------------------------------------------------------------------------
__global__ void bucket_kernel(const int* __restrict__ triples) {
    int e = blockIdx.x * blockDim.x + threadIdx.x;
    if (e >= N_EDGES) return;
    int src = triples[e * 3 + 0];
    int rel = triples[e * 3 + 1];
    int tgt = triples[e * 3 + 2];
    int b = src / SRC_BLK;
    unsigned mask = __match_any_sync(__activemask(), b);
    int lane = threadIdx.x & 31;
    int leader = __ffs(mask) - 1;
    int rank = __popc(mask & ((1u << lane) - 1));
    int base = 0;
    if (lane == leader)
        base = atomicAdd(&g_bkt_cursor[b], __popc(mask));
    base = __shfl_sync(mask, base, leader);
    float val = 1.0f / g_counts[rel * N_NODES + tgt];
    g_es[base + rank] = make_int4(src, tgt, __float_as_int(val), rel);
}

// ---------------------------------------------------------------------------
// Kernel 2b: W [r][k][o] fp32 -> Wt hi/lo [r][o][k] bf16 (transpose + split)
// ---------------------------------------------------------------------------
__global__ void split_w_kernel(const float* __restrict__ W) {
    int idx = blockIdx.x * blockDim.x + threadIdx.x;
    if (idx >= N_RELS * 128 * 128) return;
    int r = idx >> 14;
    int k = (idx >> 7) & 127;
    int o = idx & 127;
    float x = W[idx];
    __nv_bfloat16 hi = __float2bfloat16(x);
    __nv_bfloat16 lo = __float2bfloat16(x - __bfloat162float(hi));
    int dst = (r << 14) + (o << 7) + k;
    g_wt_hi[dst] = hi;
    g_wt_lo[dst] = lo;
}

// ---------------------------------------------------------------------------
// Kernel 3: split-bf16 GEMM via mma.sync: h[r] = features @ W[r]
//   CTA = 128x128 tile for one relation, 512 threads (16 warps, 32x32/warp).
// ---------------------------------------------------------------------------
__global__ void __launch_bounds__(512, 1)
gemm_mma_kernel(const float* __restrict__ A) {
    extern __shared__ char smem[];
    const int r  = blockIdx.y;
    const int m0 = blockIdx.x * 128;
    const int tid = threadIdx.x;
    const int wid = tid >> 5;
    const int lid = tid & 31;
    const uint32_t sb = smem_u32(smem);

    // ---- fill smem: A (convert fp32->bf16 hi/lo) and B (pre-split bf16) ----
    {
        const __nv_bfloat16* Bh = g_wt_hi + (r << 14);
        const __nv_bfloat16* Bl = g_wt_lo + (r << 14);
#pragma unroll
        for (int i = 0; i < 4; i++) {
            int cid = tid + i * 512;          // 2048 chunks
            int row = cid >> 4;
            int chunk = cid & 15;
            uint32_t so = sw_off(row, chunk);

            *(uint4*)(smem + SM_BH + so) = *(const uint4*)(Bh + (row << 7) + (chunk << 3));
            *(uint4*)(smem + SM_BL + so) = *(const uint4*)(Bl + (row << 7) + (chunk << 3));

            int grow = m0 + row;
            if (grow >= N_NODES) grow = 0;    // junk rows; epilogue guards
            const float* p = A + ((size_t)grow << 7) + (chunk << 3);
            float4 x0 = *(const float4*)p;
            float4 x1 = *(const float4*)(p + 4);
            float f[8] = {x0.x, x0.y, x0.z, x0.w, x1.x, x1.y, x1.z, x1.w};
            uint32_t ph[4], pl[4];
#pragma unroll
            for (int j = 0; j < 4; j++) {
                __nv_bfloat162 th, tl;
                float a = f[2 * j], b = f[2 * j + 1];
                th.x = __float2bfloat16(a);
                th.y = __float2bfloat16(b);
                tl.x = __float2bfloat16(a - __bfloat162float(th.x));
                tl.y = __float2bfloat16(b - __bfloat162float(th.y));
                ph[j] = *reinterpret_cast<uint32_t*>(&th);
                pl[j] = *reinterpret_cast<uint32_t*>(&tl);
            }
            *(uint4*)(smem + SM_AH + so) = make_uint4(ph[0], ph[1], ph[2], ph[3]);
            *(uint4*)(smem + SM_AL + so) = make_uint4(pl[0], pl[1], pl[2], pl[3]);
        }
    }
    __syncthreads();

    // ---- per-lane ldmatrix addresses (warp = 32m x 32n) ----
    const int wm = wid & 3;          // 4 m-tiles of 32 rows
    const int wn = wid >> 2;         // 4 n-tiles of 32 cols
    const int a_row = wm * 32 + (lid & 15);
    const int a_kc  = lid >> 4;
    const int a_and = a_row & 7;
    const uint32_t a_base = sb + (uint32_t)(a_row * 256);
    const int b_row = wn * 32 + ((lid >> 4) << 3) + (lid & 7);
    const int b_kc  = (lid >> 3) & 1;
    const int b_and = b_row & 7;     // invariant under +16
    const uint32_t b_base = sb + (uint32_t)(b_row * 256);

    float acc[2][4][4];
#pragma unroll
    for (int mt = 0; mt < 2; mt++)
#pragma unroll
        for (int nn = 0; nn < 4; nn++)
#pragma unroll
            for (int c = 0; c < 4; c++) acc[mt][nn][c] = 0.0f;

#pragma unroll
    for (int s = 0; s < 8; s++) {
        uint32_t Ah[2][4], Al[2][4], Bh4[2][4], Bl4[2][4];
        const uint32_t ac = (uint32_t)(((s * 2 + a_kc) ^ a_and) << 4);
        const uint32_t bc = (uint32_t)(((s * 2 + b_kc) ^ b_and) << 4);
#pragma unroll
        for (int t2 = 0; t2 < 2; t2++) {
            ldsm4(Ah[t2], a_base + SM_AH + t2 * 4096 + ac);
            ldsm4(Al[t2], a_base + SM_AL + t2 * 4096 + ac);
            ldsm4(Bh4[t2], b_base + SM_BH + t2 * 4096 + bc);
            ldsm4(Bl4[t2], b_base + SM_BL + t2 * 4096 + bc);
        }
#pragma unroll
        for (int g = 0; g < 2; g++) {
#pragma unroll
            for (int half = 0; half < 2; half++) {
                const int nn = g * 2 + half;
                const uint32_t* bh = &Bh4[g][half * 2];
                const uint32_t* bl = &Bl4[g][half * 2];
#pragma unroll
                for (int mt = 0; mt < 2; mt++) {
                    mma_bf16(acc[mt][nn], Ah[mt], bh);
                    mma_bf16(acc[mt][nn], Ah[mt], bl);
                    mma_bf16(acc[mt][nn], Al[mt], bh);
                }
            }
        }
    }

    // ---- epilogue: write fp32 h[r] tile ----
    float* H = g_h + ((size_t)r * N_NODES << 7);
    const int col0 = wn * 32 + (lid & 3) * 2;
    const int row_lo = m0 + wm * 32 + (lid >> 2);
#pragma unroll
    for (int mt = 0; mt < 2; mt++) {
        int row = row_lo + mt * 16;
        if (row < N_NODES) {
            float* Hp = H + ((size_t)row << 7) + col0;
#pragma unroll
            for (int nn = 0; nn < 4; nn++)
                *(float2*)(Hp + nn * 8) = make_float2(acc[mt][nn][0], acc[mt][nn][1]);
        }
        if (row + 8 < N_NODES) {
            float* Hp = H + ((size_t)(row + 8) << 7) + col0;
#pragma unroll
            for (int nn = 0; nn < 4; nn++)
                *(float2*)(Hp + nn * 8) = make_float2(acc[mt][nn][2], acc[mt][nn][3]);
        }
    }
}

// ---------------------------------------------------------------------------
// Kernel 4: src-block-ordered edges; 8 lanes/edge, 4 float4/lane (R3 layout)
//   out[tgt] += h[rel,src] * val
// ---------------------------------------------------------------------------
__global__ void edge_kernel(float* __restrict__ out) {
    int t = blockIdx.x * blockDim.x + threadIdx.x;
    int ei = t >> 3;
    int p = t & 7;
    if (ei >= N_EDGES) return;
    int4 q = g_es[ei];
    int src = q.x, tgt = q.y, rel = q.w;
    float val = __int_as_float(q.z);

    const float4* h4 = (const float4*)(g_h + (((size_t)rel * N_NODES + src) << 7)) + p * 4;
    float4 v0 = h4[0];
    float4 v1 = h4[1];
    float4 v2 = h4[2];
    float4 v3 = h4[3];
    v0.x *= val; v0.y *= val; v0.z *= val; v0.w *= val;
    v1.x *= val; v1.y *= val; v1.z *= val; v1.w *= val;
    v2.x *= val; v2.y *= val; v2.z *= val; v2.w *= val;
    v3.x *= val; v3.y *= val; v3.z *= val; v3.w *= val;

    float4* o = (float4*)(out + ((size_t)tgt << 7)) + p * 4;
    asm volatile("red.global.add.v4.f32 [%0], {%1, %2, %3, %4};"
                 :: "l"(o + 0), "f"(v0.x), "f"(v0.y), "f"(v0.z), "f"(v0.w) : "memory");
    asm volatile("red.global.add.v4.f32 [%0], {%1, %2, %3, %4};"
                 :: "l"(o + 1), "f"(v1.x), "f"(v1.y), "f"(v1.z), "f"(v1.w) : "memory");
    asm volatile("red.global.add.v4.f32 [%0], {%1, %2, %3, %4};"
                 :: "l"(o + 2), "f"(v2.x), "f"(v2.y), "f"(v2.z), "f"(v2.w) : "memory");
    asm volatile("red.global.add.v4.f32 [%0], {%1, %2, %3, %4};"
                 :: "l"(o + 3), "f"(v3.x), "f"(v3.y), "f"(v3.z), "f"(v3.w) : "memory");
}

// ---------------------------------------------------------------------------
extern "C" void kernel_launch(void* const* d_in, const int* in_sizes, int n_in,
                              void* d_out, int out_size) {
    const int*   triples  = (const int*)d_in[0];    // [E, 3] (src, rel, tgt)
    const float* features = (const float*)d_in[1];  // [N, 128]
    const float* weights  = (const float*)d_in[2];  // [8, 128, 128]
    const float* bias     = (const float*)d_in[3];  // [128]
    float* out = (float*)d_out;                     // [N, 128]
    (void)in_sizes; (void)n_in; (void)out_size;

    cudaFuncSetAttribute(gemm_mma_kernel,
                         cudaFuncAttributeMaxDynamicSharedMemorySize, SMEM_TOTAL);

    init_kernel<<<1024, 256>>>(out, bias);
    count_kernel<<<(N_EDGES + 255) / 256, 256>>>(triples);
    offsets_kernel<<<1, 32>>>();
    bucket_kernel<<<(N_EDGES + 255) / 256, 256>>>(triples);
    split_w_kernel<<<(N_RELS * 128 * 128 + 255) / 256, 256>>>(weights);

    dim3 gg(M_TILES, N_RELS);
    gemm_mma_kernel<<<gg, 512, SMEM_TOTAL>>>(features);

    edge_kernel<<<(N_EDGES * 8 + 511) / 512, 512>>>(out);
}

// round 10
// speedup vs baseline: 1.8030x; 1.1925x over previous
#include <cuda_runtime.h>
#include <cuda_bf16.h>
#include <cstdint>

#define N_NODES 50000
#define N_RELS  8
#define IN_DIM  128
#define OUT_DIM 128
#define N_EDGES 800000
#define M_TILES ((N_NODES + 127) / 128)   // 391

// Scratch (__device__ globals: allocation-free rule)
__device__ __align__(16) float g_h[(size_t)N_RELS * N_NODES * OUT_DIM]; // 204.8 MB
__device__ float g_counts[N_RELS * N_NODES];                            // 1.6 MB
__device__ __align__(16) __nv_bfloat16 g_wt_hi[N_RELS * 128 * 128];     // W^T hi [r][o][k]
__device__ __align__(16) __nv_bfloat16 g_wt_lo[N_RELS * 128 * 128];     // W^T lo [r][o][k]

// ---------------------------------------------------------------------------
// helpers (baseline PTX ISA — safe for plain sm_103 ptx target)
// ---------------------------------------------------------------------------
__device__ __forceinline__ uint32_t smem_u32(const void* p) {
    uint32_t a;
    asm("{ .reg .u64 t; cvta.to.shared.u64 t, %1; cvt.u32.u64 %0, t; }"
        : "=r"(a) : "l"(p));
    return a;
}

__device__ __forceinline__ void ldsm4(uint32_t* r, uint32_t addr) {
    asm volatile("ldmatrix.sync.aligned.m8n8.x4.shared.b16 {%0,%1,%2,%3}, [%4];"
                 : "=r"(r[0]), "=r"(r[1]), "=r"(r[2]), "=r"(r[3]) : "r"(addr));
}

__device__ __forceinline__ void mma_bf16(float* d, const uint32_t* a, const uint32_t* b) {
    asm volatile(
        "mma.sync.aligned.m16n8k16.row.col.f32.bf16.bf16.f32 "
        "{%0,%1,%2,%3}, {%4,%5,%6,%7}, {%8,%9}, {%0,%1,%2,%3};"
        : "+f"(d[0]), "+f"(d[1]), "+f"(d[2]), "+f"(d[3])
        : "r"(a[0]), "r"(a[1]), "r"(a[2]), "r"(a[3]), "r"(b[0]), "r"(b[1]));
}

// tile row = 256B (128 bf16) = 16 chunks of 16B; chunk' = chunk ^ (row&7)
__device__ __forceinline__ uint32_t sw_off(int row, int chunk) {
    return (uint32_t)(row * 256 + ((chunk ^ (row & 7)) << 4));
}

// SMEM: Ahi 32KB | Alo 32KB | Bhi 32KB | Blo 32KB = 128KB
#define SM_AH 0
#define SM_AL 32768
#define SM_BH 65536
#define SM_BL 98304
#define SMEM_TOTAL 131072

// ---------------------------------------------------------------------------
// Kernel 1: out = bias, counts = 0
// ---------------------------------------------------------------------------
__global__ void init_kernel(float* __restrict__ out, const float* __restrict__ bias) {
    int idx = blockIdx.x * blockDim.x + threadIdx.x;
    int stride = gridDim.x * blockDim.x;
    const int total = N_NODES * OUT_DIM;
    for (int i = idx; i < total; i += stride)
        out[i] = bias[i & (OUT_DIM - 1)];
    for (int i = idx; i < N_RELS * N_NODES; i += stride)
        g_counts[i] = 0.0f;
}

// ---------------------------------------------------------------------------
// Kernel 2: counts[rel*N + tgt] += 1
// ---------------------------------------------------------------------------
__global__ void count_kernel(const int* __restrict__ triples) {
    int e = blockIdx.x * blockDim.x + threadIdx.x;
    if (e < N_EDGES) {
        int rel = triples[e * 3 + 1];
        int tgt = triples[e * 3 + 2];
        atomicAdd(&g_counts[rel * N_NODES + tgt], 1.0f);
    }
}

// ---------------------------------------------------------------------------
// Kernel 2b: W [r][k][o] fp32 -> Wt hi/lo [r][o][k] bf16 (transpose + split)
// ---------------------------------------------------------------------------
__global__ void split_w_kernel(const float* __restrict__ W) {
    int idx = blockIdx.x * blockDim.x + threadIdx.x;
    if (idx >= N_RELS * 128 * 128) return;
    int r = idx >> 14;
    int k = (idx >> 7) & 127;
    int o = idx & 127;
    float x = W[idx];
    __nv_bfloat16 hi = __float2bfloat16(x);
    __nv_bfloat16 lo = __float2bfloat16(x - __bfloat162float(hi));
    int dst = (r << 14) + (o << 7) + k;
    g_wt_hi[dst] = hi;
    g_wt_lo[dst] = lo;
}

// ---------------------------------------------------------------------------
// Kernel 3: split-bf16 GEMM via mma.sync: h[r] = features @ W[r]
//   CTA = 128x128 tile for one relation, 512 threads (16 warps, 32x32/warp).
// ---------------------------------------------------------------------------
__global__ void __launch_bounds__(512, 1)
gemm_mma_kernel(const float* __restrict__ A) {
    extern __shared__ char smem[];
    const int r  = blockIdx.y;
    const int m0 = blockIdx.x * 128;
    const int tid = threadIdx.x;
    const int wid = tid >> 5;
    const int lid = tid & 31;
    const uint32_t sb = smem_u32(smem);

    // ---- fill smem: A (convert fp32->bf16 hi/lo) and B (pre-split bf16) ----
    {
        const __nv_bfloat16* Bh = g_wt_hi + (r << 14);
        const __nv_bfloat16* Bl = g_wt_lo + (r << 14);
#pragma unroll
        for (int i = 0; i < 4; i++) {
            int cid = tid + i * 512;          // 2048 chunks
            int row = cid >> 4;
            int chunk = cid & 15;
            uint32_t so = sw_off(row, chunk);

            *(uint4*)(smem + SM_BH + so) = *(const uint4*)(Bh + (row << 7) + (chunk << 3));
            *(uint4*)(smem + SM_BL + so) = *(const uint4*)(Bl + (row << 7) + (chunk << 3));

            int grow = m0 + row;
            if (grow >= N_NODES) grow = 0;    // junk rows; epilogue guards
            const float* p = A + ((size_t)grow << 7) + (chunk << 3);
            float4 x0 = *(const float4*)p;
            float4 x1 = *(const float4*)(p + 4);
            float f[8] = {x0.x, x0.y, x0.z, x0.w, x1.x, x1.y, x1.z, x1.w};
            uint32_t ph[4], pl[4];
#pragma unroll
            for (int j = 0; j < 4; j++) {
                __nv_bfloat162 th, tl;
                float a = f[2 * j], b = f[2 * j + 1];
                th.x = __float2bfloat16(a);
                th.y = __float2bfloat16(b);
                tl.x = __float2bfloat16(a - __bfloat162float(th.x));
                tl.y = __float2bfloat16(b - __bfloat162float(th.y));
                ph[j] = *reinterpret_cast<uint32_t*>(&th);
                pl[j] = *reinterpret_cast<uint32_t*>(&tl);
            }
            *(uint4*)(smem + SM_AH + so) = make_uint4(ph[0], ph[1], ph[2], ph[3]);
            *(uint4*)(smem + SM_AL + so) = make_uint4(pl[0], pl[1], pl[2], pl[3]);
        }
    }
    __syncthreads();

    // ---- per-lane ldmatrix addresses (warp = 32m x 32n) ----
    const int wm = wid & 3;          // 4 m-tiles of 32 rows
    const int wn = wid >> 2;         // 4 n-tiles of 32 cols
    const int a_row = wm * 32 + (lid & 15);
    const int a_kc  = lid >> 4;
    const int a_and = a_row & 7;
    const uint32_t a_base = sb + (uint32_t)(a_row * 256);
    const int b_row = wn * 32 + ((lid >> 4) << 3) + (lid & 7);
    const int b_kc  = (lid >> 3) & 1;
    const int b_and = b_row & 7;     // invariant under +16
    const uint32_t b_base = sb + (uint32_t)(b_row * 256);

    float acc[2][4][4];
#pragma unroll
    for (int mt = 0; mt < 2; mt++)
#pragma unroll
        for (int nn = 0; nn < 4; nn++)
#pragma unroll
            for (int c = 0; c < 4; c++) acc[mt][nn][c] = 0.0f;

#pragma unroll
    for (int s = 0; s < 8; s++) {
        uint32_t Ah[2][4], Al[2][4], Bh4[2][4], Bl4[2][4];
        const uint32_t ac = (uint32_t)(((s * 2 + a_kc) ^ a_and) << 4);
        const uint32_t bc = (uint32_t)(((s * 2 + b_kc) ^ b_and) << 4);
#pragma unroll
        for (int t2 = 0; t2 < 2; t2++) {
            ldsm4(Ah[t2], a_base + SM_AH + t2 * 4096 + ac);
            ldsm4(Al[t2], a_base + SM_AL + t2 * 4096 + ac);
            ldsm4(Bh4[t2], b_base + SM_BH + t2 * 4096 + bc);
            ldsm4(Bl4[t2], b_base + SM_BL + t2 * 4096 + bc);
        }
#pragma unroll
        for (int g = 0; g < 2; g++) {
#pragma unroll
            for (int half = 0; half < 2; half++) {
                const int nn = g * 2 + half;
                const uint32_t* bh = &Bh4[g][half * 2];
                const uint32_t* bl = &Bl4[g][half * 2];
#pragma unroll
                for (int mt = 0; mt < 2; mt++) {
                    mma_bf16(acc[mt][nn], Ah[mt], bh);
                    mma_bf16(acc[mt][nn], Ah[mt], bl);
                    mma_bf16(acc[mt][nn], Al[mt], bh);
                }
            }
        }
    }

    // ---- epilogue: write fp32 h[r] tile ----
    float* H = g_h + ((size_t)r * N_NODES << 7);
    const int col0 = wn * 32 + (lid & 3) * 2;
    const int row_lo = m0 + wm * 32 + (lid >> 2);
#pragma unroll
    for (int mt = 0; mt < 2; mt++) {
        int row = row_lo + mt * 16;
        if (row < N_NODES) {
            float* Hp = H + ((size_t)row << 7) + col0;
#pragma unroll
            for (int nn = 0; nn < 4; nn++)
                *(float2*)(Hp + nn * 8) = make_float2(acc[mt][nn][0], acc[mt][nn][1]);
        }
        if (row + 8 < N_NODES) {
            float* Hp = H + ((size_t)(row + 8) << 7) + col0;
#pragma unroll
            for (int nn = 0; nn < 4; nn++)
                *(float2*)(Hp + nn * 8) = make_float2(acc[mt][nn][2], acc[mt][nn][3]);
        }
    }
}

// ---------------------------------------------------------------------------
// Kernel 4: 2 edges per thread, 8 lanes/edge-pair slot.
//   All 8 independent float4 gathers (2 h-rows) issued before any RED.
//   out[tgt] += h[rel,src] / counts[rel*N+tgt]
// ---------------------------------------------------------------------------
__global__ void edge_kernel(const int* __restrict__ triples, float* __restrict__ out) {
    int t = blockIdx.x * blockDim.x + threadIdx.x;
    int gi = t >> 3;            // edge-pair index
    int p = t & 7;              // 16-float segment within row
    int e0 = gi * 2;
    if (e0 >= N_EDGES) return;
    int e1 = e0 + 1;
    bool has1 = (e1 < N_EDGES);

    int s0 = triples[e0 * 3 + 0];
    int r0 = triples[e0 * 3 + 1];
    int t0 = triples[e0 * 3 + 2];
    int s1 = has1 ? triples[e1 * 3 + 0] : s0;
    int r1 = has1 ? triples[e1 * 3 + 1] : r0;
    int t1 = has1 ? triples[e1 * 3 + 2] : t0;

    float c0 = g_counts[r0 * N_NODES + t0];
    float c1 = g_counts[r1 * N_NODES + t1];
    float val0 = 1.0f / c0;
    float val1 = 1.0f / c1;

    // issue all 8 gathers up front (MLP = 8)
    const float4* ha = (const float4*)(g_h + (((size_t)r0 * N_NODES + s0) << 7)) + p * 4;
    const float4* hb = (const float4*)(g_h + (((size_t)r1 * N_NODES + s1) << 7)) + p * 4;
    float4 a0 = ha[0], a1 = ha[1], a2 = ha[2], a3 = ha[3];
    float4 b0 = hb[0], b1 = hb[1], b2 = hb[2], b3 = hb[3];

    a0.x *= val0; a0.y *= val0; a0.z *= val0; a0.w *= val0;
    a1.x *= val0; a1.y *= val0; a1.z *= val0; a1.w *= val0;
    a2.x *= val0; a2.y *= val0; a2.z *= val0; a2.w *= val0;
    a3.x *= val0; a3.y *= val0; a3.z *= val0; a3.w *= val0;

    float4* o0 = (float4*)(out + ((size_t)t0 << 7)) + p * 4;
    asm volatile("red.global.add.v4.f32 [%0], {%1, %2, %3, %4};"
                 :: "l"(o0 + 0), "f"(a0.x), "f"(a0.y), "f"(a0.z), "f"(a0.w) : "memory");
    asm volatile("red.global.add.v4.f32 [%0], {%1, %2, %3, %4};"
                 :: "l"(o0 + 1), "f"(a1.x), "f"(a1.y), "f"(a1.z), "f"(a1.w) : "memory");
    asm volatile("red.global.add.v4.f32 [%0], {%1, %2, %3, %4};"
                 :: "l"(o0 + 2), "f"(a2.x), "f"(a2.y), "f"(a2.z), "f"(a2.w) : "memory");
    asm volatile("red.global.add.v4.f32 [%0], {%1, %2, %3, %4};"
                 :: "l"(o0 + 3), "f"(a3.x), "f"(a3.y), "f"(a3.z), "f"(a3.w) : "memory");

    if (has1) {
        b0.x *= val1; b0.y *= val1; b0.z *= val1; b0.w *= val1;
        b1.x *= val1; b1.y *= val1; b1.z *= val1; b1.w *= val1;
        b2.x *= val1; b2.y *= val1; b2.z *= val1; b2.w *= val1;
        b3.x *= val1; b3.y *= val1; b3.z *= val1; b3.w *= val1;
        float4* o1 = (float4*)(out + ((size_t)t1 << 7)) + p * 4;
        asm volatile("red.global.add.v4.f32 [%0], {%1, %2, %3, %4};"
                     :: "l"(o1 + 0), "f"(b0.x), "f"(b0.y), "f"(b0.z), "f"(b0.w) : "memory");
        asm volatile("red.global.add.v4.f32 [%0], {%1, %2, %3, %4};"
                     :: "l"(o1 + 1), "f"(b1.x), "f"(b1.y), "f"(b1.z), "f"(b1.w) : "memory");
        asm volatile("red.global.add.v4.f32 [%0], {%1, %2, %3, %4};"
                     :: "l"(o1 + 2), "f"(b2.x), "f"(b2.y), "f"(b2.z), "f"(b2.w) : "memory");
        asm volatile("red.global.add.v4.f32 [%0], {%1, %2, %3, %4};"
                     :: "l"(o1 + 3), "f"(b3.x), "f"(b3.y), "f"(b3.z), "f"(b3.w) : "memory");
    }
}

// ---------------------------------------------------------------------------
extern "C" void kernel_launch(void* const* d_in, const int* in_sizes, int n_in,
                              void* d_out, int out_size) {
    const int*   triples  = (const int*)d_in[0];    // [E, 3] (src, rel, tgt)
    const float* features = (const float*)d_in[1];  // [N, 128]
    const float* weights  = (const float*)d_in[2];  // [8, 128, 128]
    const float* bias     = (const float*)d_in[3];  // [128]
    float* out = (float*)d_out;                     // [N, 128]
    (void)in_sizes; (void)n_in; (void)out_size;

    cudaFuncSetAttribute(gemm_mma_kernel,
                         cudaFuncAttributeMaxDynamicSharedMemorySize, SMEM_TOTAL);

    init_kernel<<<1024, 256>>>(out, bias);
    count_kernel<<<(N_EDGES + 255) / 256, 256>>>(triples);
    split_w_kernel<<<(N_RELS * 128 * 128 + 255) / 256, 256>>>(weights);

    dim3 gg(M_TILES, N_RELS);
    gemm_mma_kernel<<<gg, 512, SMEM_TOTAL>>>(features);

    // 2 edges per thread, 8 threads per edge-pair
    edge_kernel<<<((N_EDGES + 1) / 2 * 8 + 511) / 512, 512>>>(triples, out);
}

// round 12
// speedup vs baseline: 2.3957x; 1.3288x over previous
#include <cuda_runtime.h>
#include <cuda_fp16.h>
#include <cstdint>

#define N_NODES 50000
#define N_RELS  8
#define IN_DIM  128
#define OUT_DIM 128
#define N_EDGES 800000
#define M_TILES ((N_NODES + 127) / 128)   // 391

// Scratch (__device__ globals: allocation-free rule)
__device__ __align__(16) __half g_h[(size_t)N_RELS * N_NODES * OUT_DIM]; // 102.4 MB fp16
__device__ float g_counts[N_RELS * N_NODES];                             // 1.6 MB
__device__ __align__(16) __half g_wt[N_RELS * 128 * 128];                // W^T fp16 [r][o][k]

// ---------------------------------------------------------------------------
// helpers (baseline PTX ISA — safe for plain sm_103 ptx target)
// ---------------------------------------------------------------------------
__device__ __forceinline__ uint32_t smem_u32(const void* p) {
    uint32_t a;
    asm("{ .reg .u64 t; cvta.to.shared.u64 t, %1; cvt.u32.u64 %0, t; }"
        : "=r"(a) : "l"(p));
    return a;
}

__device__ __forceinline__ void ldsm4(uint32_t* r, uint32_t addr) {
    asm volatile("ldmatrix.sync.aligned.m8n8.x4.shared.b16 {%0,%1,%2,%3}, [%4];"
                 : "=r"(r[0]), "=r"(r[1]), "=r"(r[2]), "=r"(r[3]) : "r"(addr));
}

__device__ __forceinline__ void mma_fp16(float* d, const uint32_t* a, const uint32_t* b) {
    asm volatile(
        "mma.sync.aligned.m16n8k16.row.col.f32.f16.f16.f32 "
        "{%0,%1,%2,%3}, {%4,%5,%6,%7}, {%8,%9}, {%0,%1,%2,%3};"
        : "+f"(d[0]), "+f"(d[1]), "+f"(d[2]), "+f"(d[3])
        : "r"(a[0]), "r"(a[1]), "r"(a[2]), "r"(a[3]), "r"(b[0]), "r"(b[1]));
}

// tile row = 256B (128 fp16) = 16 chunks of 16B; chunk' = chunk ^ (row&7)
__device__ __forceinline__ uint32_t sw_off(int row, int chunk) {
    return (uint32_t)(row * 256 + ((chunk ^ (row & 7)) << 4));
}

// SMEM: A 32KB | B 32KB = 64KB
#define SM_A 0
#define SM_B 32768
#define SMEM_TOTAL 65536

// ---------------------------------------------------------------------------
// Kernel 1: out = bias, counts = 0
// ---------------------------------------------------------------------------
__global__ void init_kernel(float* __restrict__ out, const float* __restrict__ bias) {
    int idx = blockIdx.x * blockDim.x + threadIdx.x;
    int stride = gridDim.x * blockDim.x;
    const int total = N_NODES * OUT_DIM;
    for (int i = idx; i < total; i += stride)
        out[i] = bias[i & (OUT_DIM - 1)];
    for (int i = idx; i < N_RELS * N_NODES; i += stride)
        g_counts[i] = 0.0f;
}

// ---------------------------------------------------------------------------
// Kernel 2: counts[rel*N + tgt] += 1
// ---------------------------------------------------------------------------
__global__ void count_kernel(const int* __restrict__ triples) {
    int e = blockIdx.x * blockDim.x + threadIdx.x;
    if (e < N_EDGES) {
        int rel = triples[e * 3 + 1];
        int tgt = triples[e * 3 + 2];
        atomicAdd(&g_counts[rel * N_NODES + tgt], 1.0f);
    }
}

// ---------------------------------------------------------------------------
// Kernel 2b: W [r][k][o] fp32 -> Wt fp16 [r][o][k] (transpose + convert)
// ---------------------------------------------------------------------------
__global__ void split_w_kernel(const float* __restrict__ W) {
    int idx = blockIdx.x * blockDim.x + threadIdx.x;
    if (idx >= N_RELS * 128 * 128) return;
    int r = idx >> 14;
    int k = (idx >> 7) & 127;
    int o = idx & 127;
    g_wt[(r << 14) + (o << 7) + k] = __float2half_rn(W[idx]);
}

// ---------------------------------------------------------------------------
// Kernel 3: fp16 GEMM via mma.sync: h[r] = fp16(features) @ fp16(W[r])
//   CTA = 128x128 tile for one relation, 512 threads (16 warps, 32x32/warp).
//   Output h stored fp16.
// ---------------------------------------------------------------------------
__global__ void __launch_bounds__(512, 1)
gemm_mma_kernel(const float* __restrict__ A) {
    extern __shared__ char smem[];
    const int r  = blockIdx.y;
    const int m0 = blockIdx.x * 128;
    const int tid = threadIdx.x;
    const int wid = tid >> 5;
    const int lid = tid & 31;
    const uint32_t sb = smem_u32(smem);

    // ---- fill smem: A (convert fp32->fp16) and B (pre-converted fp16) ----
    {
        const __half* B = g_wt + (r << 14);
#pragma unroll
        for (int i = 0; i < 4; i++) {
            int cid = tid + i * 512;          // 2048 chunks
            int row = cid >> 4;
            int chunk = cid & 15;
            uint32_t so = sw_off(row, chunk);

            *(uint4*)(smem + SM_B + so) = *(const uint4*)(B + (row << 7) + (chunk << 3));

            int grow = m0 + row;
            if (grow >= N_NODES) grow = 0;    // junk rows; epilogue guards
            const float* p = A + ((size_t)grow << 7) + (chunk << 3);
            float4 x0 = *(const float4*)p;
            float4 x1 = *(const float4*)(p + 4);
            uint32_t pk[4];
            __half2 h0 = __floats2half2_rn(x0.x, x0.y);
            __half2 h1 = __floats2half2_rn(x0.z, x0.w);
            __half2 h2 = __floats2half2_rn(x1.x, x1.y);
            __half2 h3 = __floats2half2_rn(x1.z, x1.w);
            pk[0] = *reinterpret_cast<uint32_t*>(&h0);
            pk[1] = *reinterpret_cast<uint32_t*>(&h1);
            pk[2] = *reinterpret_cast<uint32_t*>(&h2);
            pk[3] = *reinterpret_cast<uint32_t*>(&h3);
            *(uint4*)(smem + SM_A + so) = make_uint4(pk[0], pk[1], pk[2], pk[3]);
        }
    }
    __syncthreads();

    // ---- per-lane ldmatrix addresses (warp = 32m x 32n) ----
    const int wm = wid & 3;          // 4 m-tiles of 32 rows
    const int wn = wid >> 2;         // 4 n-tiles of 32 cols
    const int a_row = wm * 32 + (lid & 15);
    const int a_kc  = lid >> 4;
    const int a_and = a_row & 7;
    const uint32_t a_base = sb + (uint32_t)(a_row * 256);
    const int b_row = wn * 32 + ((lid >> 4) << 3) + (lid & 7);
    const int b_kc  = (lid >> 3) & 1;
    const int b_and = b_row & 7;     // invariant under +16
    const uint32_t b_base = sb + (uint32_t)(b_row * 256);

    float acc[2][4][4];
#pragma unroll
    for (int mt = 0; mt < 2; mt++)
#pragma unroll
        for (int nn = 0; nn < 4; nn++)
#pragma unroll
            for (int c = 0; c < 4; c++) acc[mt][nn][c] = 0.0f;

#pragma unroll
    for (int s = 0; s < 8; s++) {
        uint32_t Ah[2][4], Bh4[2][4];
        const uint32_t ac = (uint32_t)(((s * 2 + a_kc) ^ a_and) << 4);
        const uint32_t bc = (uint32_t)(((s * 2 + b_kc) ^ b_and) << 4);
#pragma unroll
        for (int t2 = 0; t2 < 2; t2++) {
            ldsm4(Ah[t2], a_base + SM_A + t2 * 4096 + ac);
            ldsm4(Bh4[t2], b_base + SM_B + t2 * 4096 + bc);
        }
#pragma unroll
        for (int g = 0; g < 2; g++) {
#pragma unroll
            for (int half = 0; half < 2; half++) {
                const int nn = g * 2 + half;
                const uint32_t* bh = &Bh4[g][half * 2];
#pragma unroll
                for (int mt = 0; mt < 2; mt++)
                    mma_fp16(acc[mt][nn], Ah[mt], bh);
            }
        }
    }

    // ---- epilogue: write fp16 h[r] tile ----
    __half* H = g_h + ((size_t)r * N_NODES << 7);
    const int col0 = wn * 32 + (lid & 3) * 2;
    const int row_lo = m0 + wm * 32 + (lid >> 2);
#pragma unroll
    for (int mt = 0; mt < 2; mt++) {
        int row = row_lo + mt * 16;
        if (row < N_NODES) {
            __half* Hp = H + ((size_t)row << 7) + col0;
#pragma unroll
            for (int nn = 0; nn < 4; nn++) {
                __half2 hv = __floats2half2_rn(acc[mt][nn][0], acc[mt][nn][1]);
                *(uint32_t*)(Hp + nn * 8) = *reinterpret_cast<uint32_t*>(&hv);
            }
        }
        if (row + 8 < N_NODES) {
            __half* Hp = H + ((size_t)(row + 8) << 7) + col0;
#pragma unroll
            for (int nn = 0; nn < 4; nn++) {
                __half2 hv = __floats2half2_rn(acc[mt][nn][2], acc[mt][nn][3]);
                *(uint32_t*)(Hp + nn * 8) = *reinterpret_cast<uint32_t*>(&hv);
            }
        }
    }
}

// ---------------------------------------------------------------------------
// Kernel 4: 2 edges per thread, 8 lanes/edge slot; h rows are fp16 (256B).
//   All 4 independent uint4 gathers issued before any RED.
//   out[tgt] += h[rel,src] / counts[rel*N+tgt]   (fp32 RED)
// ---------------------------------------------------------------------------
__global__ void edge_kernel(const int* __restrict__ triples, float* __restrict__ out) {
    int t = blockIdx.x * blockDim.x + threadIdx.x;
    int gi = t >> 3;            // edge-pair index
    int p = t & 7;              // 16-float segment within row
    int e0 = gi * 2;
    if (e0 >= N_EDGES) return;
    int e1 = e0 + 1;
    bool has1 = (e1 < N_EDGES);

    int s0 = triples[e0 * 3 + 0];
    int r0 = triples[e0 * 3 + 1];
    int t0 = triples[e0 * 3 + 2];
    int s1 = has1 ? triples[e1 * 3 + 0] : s0;
    int r1 = has1 ? triples[e1 * 3 + 1] : r0;
    int t1 = has1 ? triples[e1 * 3 + 2] : t0;

    float val0 = 1.0f / g_counts[r0 * N_NODES + t0];
    float val1 = 1.0f / g_counts[r1 * N_NODES + t1];

    // issue all 4 gathers up front (2 per h row)
    const uint4* ha = (const uint4*)(g_h + (((size_t)r0 * N_NODES + s0) << 7)) + p * 2;
    const uint4* hb = (const uint4*)(g_h + (((size_t)r1 * N_NODES + s1) << 7)) + p * 2;
    uint4 A0 = ha[0], A1 = ha[1];
    uint4 B0 = hb[0], B1 = hb[1];

    float4* o0 = (float4*)(out + ((size_t)t0 << 7)) + p * 4;
#pragma unroll
    for (int q = 0; q < 4; q++) {
        uint32_t lo = (q < 2) ? ((q == 0) ? A0.x : A0.z) : ((q == 2) ? A1.x : A1.z);
        uint32_t hi = (q < 2) ? ((q == 0) ? A0.y : A0.w) : ((q == 2) ? A1.y : A1.w);
        float2 fa = __half22float2(*reinterpret_cast<__half2*>(&lo));
        float2 fb = __half22float2(*reinterpret_cast<__half2*>(&hi));
        asm volatile("red.global.add.v4.f32 [%0], {%1, %2, %3, %4};"
                     :: "l"(o0 + q),
                        "f"(fa.x * val0), "f"(fa.y * val0),
                        "f"(fb.x * val0), "f"(fb.y * val0) : "memory");
    }

    if (has1) {
        float4* o1 = (float4*)(out + ((size_t)t1 << 7)) + p * 4;
#pragma unroll
        for (int q = 0; q < 4; q++) {
            uint32_t lo = (q < 2) ? ((q == 0) ? B0.x : B0.z) : ((q == 2) ? B1.x : B1.z);
            uint32_t hi = (q < 2) ? ((q == 0) ? B0.y : B0.w) : ((q == 2) ? B1.y : B1.w);
            float2 fa = __half22float2(*reinterpret_cast<__half2*>(&lo));
            float2 fb = __half22float2(*reinterpret_cast<__half2*>(&hi));
            asm volatile("red.global.add.v4.f32 [%0], {%1, %2, %3, %4};"
                         :: "l"(o1 + q),
                            "f"(fa.x * val1), "f"(fa.y * val1),
                            "f"(fb.x * val1), "f"(fb.y * val1) : "memory");
        }
    }
}

// ---------------------------------------------------------------------------
extern "C" void kernel_launch(void* const* d_in, const int* in_sizes, int n_in,
                              void* d_out, int out_size) {
    const int*   triples  = (const int*)d_in[0];    // [E, 3] (src, rel, tgt)
    const float* features = (const float*)d_in[1];  // [N, 128]
    const float* weights  = (const float*)d_in[2];  // [8, 128, 128]
    const float* bias     = (const float*)d_in[3];  // [128]
    float* out = (float*)d_out;                     // [N, 128]
    (void)in_sizes; (void)n_in; (void)out_size;

    cudaFuncSetAttribute(gemm_mma_kernel,
                         cudaFuncAttributeMaxDynamicSharedMemorySize, SMEM_TOTAL);

    init_kernel<<<1024, 256>>>(out, bias);
    count_kernel<<<(N_EDGES + 255) / 256, 256>>>(triples);
    split_w_kernel<<<(N_RELS * 128 * 128 + 255) / 256, 256>>>(weights);

    dim3 gg(M_TILES, N_RELS);
    gemm_mma_kernel<<<gg, 512, SMEM_TOTAL>>>(features);

    // 2 edges per thread, 8 threads per edge-pair
    edge_kernel<<<((N_EDGES + 1) / 2 * 8 + 511) / 512, 512>>>(triples, out);
}